// round 9
// baseline (speedup 1.0000x reference)
#include <cuda_runtime.h>
#include <cuda_fp16.h>
#include <math.h>
#include <stdint.h>

#define NT 8192
#define DIMK 4096
#define NE 64
#define TOPK 8
#define RSCALE 2.5f
#define NCHUNK 64
#define NCTA 256
#define NTHR 256
#define TPC 32                 // tokens per CTA
#define SM_A 0                 // A tiles: 2 bufs x 3 terms x 4096
#define SM_W 24576             // W frags: 2 bufs x 3 terms x 8192
#define DSMEM 73728
#define INV2048 4.8828125e-4f
#define INV2048SQ 2.384185791015625e-7f

__device__ uint2 w_img[NCHUNK * 3072];  // 1.5MB frag-layout 3-way W split

__device__ __forceinline__ uint32_t swz(uint32_t x) { return x ^ ((x >> 3) & 0x70u); }
__device__ __forceinline__ uint32_t smem_u32(const void* p) {
    uint32_t a;
    asm("{ .reg .u64 t; cvta.to.shared.u64 t, %1; cvt.u32.u64 %0, t; }" : "=r"(a) : "l"(p));
    return a;
}
#define LDM(R, a) asm volatile( \
    "ldmatrix.sync.aligned.m8n8.x4.shared.b16 {%0,%1,%2,%3}, [%4];" \
    : "=r"((R)[0]), "=r"((R)[1]), "=r"((R)[2]), "=r"((R)[3]) : "r"(a))
#define MMA(C, A, B0, B1) asm volatile( \
    "mma.sync.aligned.m16n8k16.row.col.f32.f16.f16.f32 " \
    "{%0,%1,%2,%3},{%4,%5,%6,%7},{%8,%9},{%0,%1,%2,%3};" \
    : "+f"((C)[0]), "+f"((C)[1]), "+f"((C)[2]), "+f"((C)[3]) \
    : "r"((A)[0]), "r"((A)[1]), "r"((A)[2]), "r"((A)[3]), "r"(B0), "r"(B1))
#define LDS64(r0, r1, a) asm volatile("ld.shared.v2.u32 {%0,%1}, [%2];" \
    : "=r"(r0), "=r"(r1) : "r"(a))
#define CPA(d, s) asm volatile("cp.async.cg.shared.global [%0], [%1], 16;" :: "r"(d), "l"(s))
#define CPC() asm volatile("cp.async.commit_group;" ::: "memory")
#define CPW0() asm volatile("cp.async.wait_group 0;" ::: "memory")

// exact 3-way fp16 split: v = a + b/2048 + c/2048^2 (+ O(2^-33))
__device__ __forceinline__ void split3(float v, __half& a, __half& b, __half& c) {
    a = __float2half_rn(v);
    float r1 = v - __half2float(a);
    b = __float2half_rn(r1 * 2048.0f);
    float r2 = r1 - __half2float(b) * INV2048;
    c = __float2half_rn(r2 * 4194304.0f);
}

// W split into B-fragment-order image; also zeroes the histogram region
__global__ void wprep_kernel(const float* __restrict__ w, float* __restrict__ out) {
    int idx = blockIdx.x * blockDim.x + threadIdx.x;
    if (idx < NE) out[2 * NT * TOPK + idx] = 0.0f;
    if (idx >= NCHUNK * 3072) return;
    int c = idx / 3072, rem = idx % 3072;
    int t = rem >> 10;
    int rem2 = rem & 1023;
    int s = (rem2 >> 8) & 3, j = (rem2 >> 5) & 7, lane = rem2 & 31;
    int e = j * 8 + (lane >> 2);
    int k0 = c * 64 + s * 16 + (lane & 3) * 2;
    __half h[4];
    #pragma unroll
    for (int i = 0; i < 4; i++) {
        int k = k0 + (i >> 1) * 8 + (i & 1);
        __half ha, hb, hc;
        split3(w[e * DIMK + k], ha, hb, hc);
        h[i] = (t == 0) ? ha : (t == 1 ? hb : hc);
    }
    uint2 o;
    o.x = (uint32_t)__half_as_ushort(h[0]) | ((uint32_t)__half_as_ushort(h[1]) << 16);
    o.y = (uint32_t)__half_as_ushort(h[2]) | ((uint32_t)__half_as_ushort(h[3]) << 16);
    w_img[idx] = o;
}

__global__ void __launch_bounds__(NTHR, 2)
router_kernel(const float* __restrict__ x, const float* __restrict__ bias,
              float* __restrict__ out) {
    extern __shared__ char smem[];
    __shared__ int shist[NE];
    const uint32_t sb = smem_u32(smem);
    const int tid = threadIdx.x, wid = tid >> 5, lane = tid & 31;
    const int blockRow = blockIdx.x * TPC;
    const int pr = tid >> 3, pq = tid & 7;              // producer: row, 8-float col group
    const int mb = (wid & 1) * 16;                      // m-tile
    const int nh = (wid >> 1) & 1;                      // n-half
    const int ks = wid >> 2;                            // k-half

    if (tid < NE) shist[tid] = 0;

    float Cs[4][4], Cf1[4][4], Cf2[4][4], C2[4][4], C3[4][4];
    #pragma unroll
    for (int j = 0; j < 4; j++)
        #pragma unroll
        for (int v = 0; v < 4; v++) {
            Cs[j][v] = 0; Cf1[j][v] = 0; Cf2[j][v] = 0; C2[j][v] = 0; C3[j][v] = 0;
        }

    // preload W chunk0 + x chunk0
    {
        const char* src = (const char*)w_img + (size_t)tid * 96;
        uint32_t dst = sb + SM_W + tid * 96;
        #pragma unroll
        for (int q = 0; q < 6; q++) CPA(dst + q * 16, src + q * 16);
        CPC();
    }
    float4 xc[2], xn[2];
    #pragma unroll
    for (int i = 0; i < 2; i++)
        xc[i] = *reinterpret_cast<const float4*>(
            &x[(size_t)(blockRow + pr) * DIMK + pq * 8 + i * 4]);

    const uint32_t lrow = (lane & 7) + ((lane >> 3) & 1) * 8;
    const uint32_t lcol16 = ((lane >> 4) & 1) * 16;

    for (int it = 0; it < NCHUNK; ++it) {
        const int b = it & 1;
        if (it + 1 < NCHUNK) {
            const int kb = (it + 1) * 64;
            #pragma unroll
            for (int i = 0; i < 2; i++)
                xn[i] = *reinterpret_cast<const float4*>(
                    &x[(size_t)(blockRow + pr) * DIMK + kb + pq * 8 + i * 4]);
        }
        // convert + store 3 A tiles (swizzled): 8 fp32 -> 4 packed half2 per term
        {
            uint32_t aw[4], bw[4], cw[4];
            #pragma unroll
            for (int i = 0; i < 2; i++) {
                const float vv[4] = {xc[i].x, xc[i].y, xc[i].z, xc[i].w};
                #pragma unroll
                for (int p = 0; p < 2; p++) {
                    __half a0, b0, c0, a1, b1, c1;
                    split3(vv[p * 2], a0, b0, c0);
                    split3(vv[p * 2 + 1], a1, b1, c1);
                    aw[i * 2 + p] = (uint32_t)__half_as_ushort(a0) |
                                    ((uint32_t)__half_as_ushort(a1) << 16);
                    bw[i * 2 + p] = (uint32_t)__half_as_ushort(b0) |
                                    ((uint32_t)__half_as_ushort(b1) << 16);
                    cw[i * 2 + p] = (uint32_t)__half_as_ushort(c0) |
                                    ((uint32_t)__half_as_ushort(c1) << 16);
                }
            }
            uint32_t off = pr * 128 + pq * 16;
            char* A = smem + SM_A + b * 12288;
            *(uint4*)(A + swz(off))        = make_uint4(aw[0], aw[1], aw[2], aw[3]);
            *(uint4*)(A + 4096 + swz(off)) = make_uint4(bw[0], bw[1], bw[2], bw[3]);
            *(uint4*)(A + 8192 + swz(off)) = make_uint4(cw[0], cw[1], cw[2], cw[3]);
        }
        CPW0();
        __syncthreads();
        if (it + 1 < NCHUNK) {
            const char* src = (const char*)w_img + (size_t)(it + 1) * 24576 + tid * 96;
            uint32_t dst = sb + SM_W + (b ^ 1) * 24576 + tid * 96;
            #pragma unroll
            for (int q = 0; q < 6; q++) CPA(dst + q * 16, src + q * 16);
            CPC();
        }
        // consume: this warp covers m16 x n32 x k32 (its k-half)
        {
            const uint32_t Abase = sb + SM_A + b * 12288;
            const uint32_t Wbase = sb + SM_W + b * 24576;
            #pragma unroll
            for (int s2 = 0; s2 < 2; s2++) {
                const int sidx = ks * 2 + s2;
                uint32_t fa[4], fb[4], fc[4];
                uint32_t aoff = swz((mb + lrow) * 128 + sidx * 32 + lcol16);
                LDM(fa, Abase + aoff);
                LDM(fb, Abase + 4096 + aoff);
                LDM(fc, Abase + 8192 + aoff);
                #pragma unroll
                for (int jl = 0; jl < 4; jl++) {
                    uint32_t wi = ((sidx * 8 + nh * 4 + jl) * 32 + lane) * 8;
                    uint32_t wa0, wa1, wb0, wb1, wc0, wc1;
                    LDS64(wa0, wa1, Wbase + wi);
                    LDS64(wb0, wb1, Wbase + 8192 + wi);
                    LDS64(wc0, wc1, Wbase + 16384 + wi);
                    MMA(Cs[jl], fa, wa0, wa1);
                    MMA(C2[jl], fa, wb0, wb1);
                    MMA(C2[jl], fb, wa0, wa1);
                    MMA(C3[jl], fb, wb0, wb1);
                    MMA(C3[jl], fa, wc0, wc1);
                    MMA(C3[jl], fc, wa0, wa1);
                }
            }
        }
        if (it & 1) {
            #pragma unroll
            for (int j = 0; j < 4; j++)
                #pragma unroll
                for (int v = 0; v < 4; v++) { Cf1[j][v] += Cs[j][v]; Cs[j][v] = 0; }
        }
        if ((it & 7) == 7) {
            #pragma unroll
            for (int j = 0; j < 4; j++)
                #pragma unroll
                for (int v = 0; v < 4; v++) { Cf2[j][v] += Cf1[j][v]; Cf1[j][v] = 0; }
        }
        #pragma unroll
        for (int i = 0; i < 2; i++) xc[i] = xn[i];
    }

    // logits [32][65] in W buf0 region; two-phase combine of k-half partials
    float* logits = reinterpret_cast<float*>(smem + SM_W);
    if (ks == 0) {
        #pragma unroll
        for (int jl = 0; jl < 4; jl++) {
            const int r0 = mb + (lane >> 2);
            const int c0 = nh * 32 + jl * 8 + (lane & 3) * 2;
            #pragma unroll
            for (int v = 0; v < 4; v++) {
                const int rr = r0 + (v >> 1) * 8, cc = c0 + (v & 1);
                logits[rr * 65 + cc] =
                    Cf2[jl][v] + C2[jl][v] * INV2048 + C3[jl][v] * INV2048SQ;
            }
        }
    }
    __syncthreads();
    if (ks == 1) {
        #pragma unroll
        for (int jl = 0; jl < 4; jl++) {
            const int r0 = mb + (lane >> 2);
            const int c0 = nh * 32 + jl * 8 + (lane & 3) * 2;
            #pragma unroll
            for (int v = 0; v < 4; v++) {
                const int rr = r0 + (v >> 1) * 8, cc = c0 + (v & 1);
                logits[rr * 65 + cc] +=
                    Cf2[jl][v] + C2[jl][v] * INV2048 + C3[jl][v] * INV2048SQ;
            }
        }
    }
    __syncthreads();

    // routing: 8 warps x 4 tokens
    const float bias0 = bias[lane];
    const float bias1 = bias[lane + 32];
    for (int tt = wid * 4; tt < wid * 4 + 4; tt++) {
        const float l0 = logits[tt * 65 + lane];
        const float l1 = logits[tt * 65 + lane + 32];
        const float s0 = 1.0f / (1.0f + expf(-l0));
        const float s1 = 1.0f / (1.0f + expf(-l1));
        float b0 = s0 + bias0, b1 = s1 + bias1;
        float denom = 0.0f, selVal = 0.0f;
        int selIdx = 0;
        #pragma unroll
        for (int k = 0; k < TOPK; k++) {
            float v = b0; int ix = lane;
            if (b1 > v) { v = b1; ix = lane + 32; }
            #pragma unroll
            for (int off = 16; off > 0; off >>= 1) {
                const float ov = __shfl_xor_sync(0xffffffffu, v, off);
                const int   oi = __shfl_xor_sync(0xffffffffu, ix, off);
                if (ov > v || (ov == v && oi < ix)) { v = ov; ix = oi; }
            }
            const float g0 = __shfl_sync(0xffffffffu, s0, ix & 31);
            const float g1 = __shfl_sync(0xffffffffu, s1, ix & 31);
            const float sv = (ix < 32) ? g0 : g1;
            denom += sv;
            if (lane == k) { selVal = sv; selIdx = ix; }
            if (lane == (ix & 31)) { if (ix < 32) b0 = -INFINITY; else b1 = -INFINITY; }
            if (lane == 0) atomicAdd(&shist[ix], 1);
        }
        const float scale = RSCALE / (denom + 1e-20f);
        const int tg = blockRow + tt;
        if (lane < TOPK) {
            out[tg * TOPK + lane]             = selVal * scale;
            out[NT * TOPK + tg * TOPK + lane] = (float)selIdx;
        }
    }
    __syncthreads();
    if (tid < NE) atomicAdd(&out[2 * NT * TOPK + tid], (float)shist[tid]);
}

extern "C" void kernel_launch(void* const* d_in, const int* in_sizes, int n_in,
                              void* d_out, int out_size) {
    const float* x    = (const float*)d_in[0];
    const float* w    = (const float*)d_in[1];
    const float* bias = (const float*)d_in[2];
    float* out = (float*)d_out;

    cudaFuncSetAttribute(router_kernel,
                         cudaFuncAttributeMaxDynamicSharedMemorySize, DSMEM);
    wprep_kernel<<<(NCHUNK * 3072 + 255) / 256, 256>>>(w, out);
    router_kernel<<<NCTA, NTHR, DSMEM>>>(x, bias, out);
}

// round 10
// speedup vs baseline: 1.2197x; 1.2197x over previous
#include <cuda_runtime.h>
#include <cuda_fp16.h>
#include <math.h>
#include <stdint.h>

#define NT 8192
#define DIMK 4096
#define NE 64
#define TOPK 8
#define RSCALE 2.5f
#define NCHUNK 64
#define NCTA 128
#define NTHR 512
#define TPC 64
#define SM_A 0            // A tiles: 2 bufs x 3 terms x 8192
#define SM_W 49152        // W frags: 2 bufs x 3 terms x 8192
#define DSMEM 98304
#define INV2048 4.8828125e-4f
#define INV2048SQ 2.384185791015625e-7f

__device__ uint2 w_img[NCHUNK * 3072];  // 1.5MB frag-layout 3-way W split

__device__ __forceinline__ uint32_t swz(uint32_t x) { return x ^ ((x >> 3) & 0x70u); }
__device__ __forceinline__ uint32_t smem_u32(const void* p) {
    uint32_t a;
    asm("{ .reg .u64 t; cvta.to.shared.u64 t, %1; cvt.u32.u64 %0, t; }" : "=r"(a) : "l"(p));
    return a;
}
#define LDM(R, a) asm volatile( \
    "ldmatrix.sync.aligned.m8n8.x4.shared.b16 {%0,%1,%2,%3}, [%4];" \
    : "=r"((R)[0]), "=r"((R)[1]), "=r"((R)[2]), "=r"((R)[3]) : "r"(a))
#define MMA(C, A, B0, B1) asm volatile( \
    "mma.sync.aligned.m16n8k16.row.col.f32.f16.f16.f32 " \
    "{%0,%1,%2,%3},{%4,%5,%6,%7},{%8,%9},{%0,%1,%2,%3};" \
    : "+f"((C)[0]), "+f"((C)[1]), "+f"((C)[2]), "+f"((C)[3]) \
    : "r"((A)[0]), "r"((A)[1]), "r"((A)[2]), "r"((A)[3]), "r"(B0), "r"(B1))
#define LDS64(r0, r1, a) asm volatile("ld.shared.v2.u32 {%0,%1}, [%2];" \
    : "=r"(r0), "=r"(r1) : "r"(a))
#define CPA(d, s) asm volatile("cp.async.cg.shared.global [%0], [%1], 16;" :: "r"(d), "l"(s))
#define CPC() asm volatile("cp.async.commit_group;" ::: "memory")
#define CPW0() asm volatile("cp.async.wait_group 0;" ::: "memory")

// exact 3-way fp16 split: v = a + b/2048 + c/2048^2 (+ O(2^-33))
__device__ __forceinline__ void split3(float v, __half& a, __half& b, __half& c) {
    a = __float2half_rn(v);
    float r1 = v - __half2float(a);
    b = __float2half_rn(r1 * 2048.0f);
    float r2 = r1 - __half2float(b) * INV2048;
    c = __float2half_rn(r2 * 4194304.0f);
}

// W split into B-fragment-order image; also zeroes the histogram region
__global__ void wprep_kernel(const float* __restrict__ w, float* __restrict__ out) {
    int idx = blockIdx.x * blockDim.x + threadIdx.x;
    if (idx < NE) out[2 * NT * TOPK + idx] = 0.0f;
    if (idx >= NCHUNK * 3072) return;
    int c = idx / 3072, rem = idx % 3072;
    int t = rem >> 10;
    int rem2 = rem & 1023;
    int s = (rem2 >> 8) & 3, j = (rem2 >> 5) & 7, lane = rem2 & 31;
    int e = j * 8 + (lane >> 2);
    int k0 = c * 64 + s * 16 + (lane & 3) * 2;
    __half h[4];
    #pragma unroll
    for (int i = 0; i < 4; i++) {
        int k = k0 + (i >> 1) * 8 + (i & 1);
        __half ha, hb, hc;
        split3(w[e * DIMK + k], ha, hb, hc);
        h[i] = (t == 0) ? ha : (t == 1 ? hb : hc);
    }
    uint2 o;
    o.x = (uint32_t)__half_as_ushort(h[0]) | ((uint32_t)__half_as_ushort(h[1]) << 16);
    o.y = (uint32_t)__half_as_ushort(h[2]) | ((uint32_t)__half_as_ushort(h[3]) << 16);
    w_img[idx] = o;
}

__global__ void __launch_bounds__(NTHR, 1)
router_kernel(const float* __restrict__ x, const float* __restrict__ bias,
              float* __restrict__ out) {
    extern __shared__ char smem[];
    __shared__ int shist[NE];
    const uint32_t sb = smem_u32(smem);
    const int tid = threadIdx.x, wid = tid >> 5, lane = tid & 31;
    const int blockRow = blockIdx.x * TPC;
    const int pr = tid >> 3, pq = tid & 7;   // producer: row 0..63, 8-float col group
    const int mb = (wid & 3) * 16;           // m-tile (4)
    const int nh = (wid >> 2) & 1;           // n-half (2)
    const int ks = wid >> 3;                 // k-half (2)

    if (tid < NE) shist[tid] = 0;

    float Cs[4][4], Cf[4][4], C2[4][4], C3[4][4];
    #pragma unroll
    for (int j = 0; j < 4; j++)
        #pragma unroll
        for (int v = 0; v < 4; v++) { Cs[j][v] = 0; Cf[j][v] = 0; C2[j][v] = 0; C3[j][v] = 0; }

    // preload W chunk0 (48B per thread) + x chunk0
    {
        const char* src = (const char*)w_img + (size_t)tid * 48;
        uint32_t dst = sb + SM_W + tid * 48;
        #pragma unroll
        for (int q = 0; q < 3; q++) CPA(dst + q * 16, src + q * 16);
        CPC();
    }
    float4 xc[2], xn[2];
    #pragma unroll
    for (int i = 0; i < 2; i++)
        xc[i] = *reinterpret_cast<const float4*>(
            &x[(size_t)(blockRow + pr) * DIMK + pq * 8 + i * 4]);

    const uint32_t lrow = (lane & 7) + ((lane >> 3) & 1) * 8;
    const uint32_t lcol16 = ((lane >> 4) & 1) * 16;

    for (int it = 0; it < NCHUNK; ++it) {
        const int b = it & 1;
        if (it + 1 < NCHUNK) {
            const int kb = (it + 1) * 64;
            #pragma unroll
            for (int i = 0; i < 2; i++)
                xn[i] = *reinterpret_cast<const float4*>(
                    &x[(size_t)(blockRow + pr) * DIMK + kb + pq * 8 + i * 4]);
        }
        // convert + store 3 A tiles (swizzled): 8 fp32 -> 4 half2 per term
        {
            uint32_t aw[4], bw[4], cw[4];
            #pragma unroll
            for (int i = 0; i < 2; i++) {
                const float vv[4] = {xc[i].x, xc[i].y, xc[i].z, xc[i].w};
                #pragma unroll
                for (int p = 0; p < 2; p++) {
                    __half a0, b0, c0, a1, b1, c1;
                    split3(vv[p * 2], a0, b0, c0);
                    split3(vv[p * 2 + 1], a1, b1, c1);
                    aw[i * 2 + p] = (uint32_t)__half_as_ushort(a0) |
                                    ((uint32_t)__half_as_ushort(a1) << 16);
                    bw[i * 2 + p] = (uint32_t)__half_as_ushort(b0) |
                                    ((uint32_t)__half_as_ushort(b1) << 16);
                    cw[i * 2 + p] = (uint32_t)__half_as_ushort(c0) |
                                    ((uint32_t)__half_as_ushort(c1) << 16);
                }
            }
            uint32_t off = pr * 128 + pq * 16;
            char* A = smem + SM_A + b * 24576;
            *(uint4*)(A + swz(off))         = make_uint4(aw[0], aw[1], aw[2], aw[3]);
            *(uint4*)(A + 8192 + swz(off))  = make_uint4(bw[0], bw[1], bw[2], bw[3]);
            *(uint4*)(A + 16384 + swz(off)) = make_uint4(cw[0], cw[1], cw[2], cw[3]);
        }
        CPW0();
        __syncthreads();
        if (it + 1 < NCHUNK) {
            const char* src = (const char*)w_img + (size_t)(it + 1) * 24576 + tid * 48;
            uint32_t dst = sb + SM_W + (b ^ 1) * 24576 + tid * 48;
            #pragma unroll
            for (int q = 0; q < 3; q++) CPA(dst + q * 16, src + q * 16);
            CPC();
        }
        // consume: warp covers m16 x n32 x k32 (its k-half)
        {
            const uint32_t Abase = sb + SM_A + b * 24576;
            const uint32_t Wbase = sb + SM_W + b * 24576;
            #pragma unroll
            for (int s2 = 0; s2 < 2; s2++) {
                const int sidx = ks * 2 + s2;
                uint32_t fa[4], fb[4], fc[4];
                uint32_t aoff = swz((mb + lrow) * 128 + sidx * 32 + lcol16);
                LDM(fa, Abase + aoff);
                LDM(fb, Abase + 8192 + aoff);
                LDM(fc, Abase + 16384 + aoff);
                #pragma unroll
                for (int jl = 0; jl < 4; jl++) {
                    uint32_t wi = ((sidx * 8 + nh * 4 + jl) * 32 + lane) * 8;
                    uint32_t wa0, wa1, wb0, wb1, wc0, wc1;
                    LDS64(wa0, wa1, Wbase + wi);
                    LDS64(wb0, wb1, Wbase + 8192 + wi);
                    LDS64(wc0, wc1, Wbase + 16384 + wi);
                    MMA(Cs[jl], fa, wa0, wa1);
                    MMA(C2[jl], fa, wb0, wb1);
                    MMA(C2[jl], fb, wa0, wa1);
                    MMA(C3[jl], fb, wb0, wb1);
                    MMA(C3[jl], fa, wc0, wc1);
                    MMA(C3[jl], fc, wa0, wa1);
                }
            }
        }
        if ((it & 3) == 3) {
            #pragma unroll
            for (int j = 0; j < 4; j++)
                #pragma unroll
                for (int v = 0; v < 4; v++) { Cf[j][v] += Cs[j][v]; Cs[j][v] = 0; }
        }
        #pragma unroll
        for (int i = 0; i < 2; i++) xc[i] = xn[i];
    }

    // logits [64][65] in W region; two-phase combine of k-half partials
    float* logits = reinterpret_cast<float*>(smem + SM_W);
    if (ks == 0) {
        #pragma unroll
        for (int jl = 0; jl < 4; jl++) {
            const int r0 = mb + (lane >> 2);
            const int c0 = nh * 32 + jl * 8 + (lane & 3) * 2;
            #pragma unroll
            for (int v = 0; v < 4; v++) {
                const int rr = r0 + (v >> 1) * 8, cc = c0 + (v & 1);
                logits[rr * 65 + cc] =
                    Cf[jl][v] + C2[jl][v] * INV2048 + C3[jl][v] * INV2048SQ;
            }
        }
    }
    __syncthreads();
    if (ks == 1) {
        #pragma unroll
        for (int jl = 0; jl < 4; jl++) {
            const int r0 = mb + (lane >> 2);
            const int c0 = nh * 32 + jl * 8 + (lane & 3) * 2;
            #pragma unroll
            for (int v = 0; v < 4; v++) {
                const int rr = r0 + (v >> 1) * 8, cc = c0 + (v & 1);
                logits[rr * 65 + cc] +=
                    Cf[jl][v] + C2[jl][v] * INV2048 + C3[jl][v] * INV2048SQ;
            }
        }
    }
    __syncthreads();

    // routing: 16 warps x 4 tokens
    const float bias0 = bias[lane];
    const float bias1 = bias[lane + 32];
    for (int tt = wid * 4; tt < wid * 4 + 4; tt++) {
        const float l0 = logits[tt * 65 + lane];
        const float l1 = logits[tt * 65 + lane + 32];
        const float s0 = 1.0f / (1.0f + expf(-l0));
        const float s1 = 1.0f / (1.0f + expf(-l1));
        float b0 = s0 + bias0, b1 = s1 + bias1;
        float denom = 0.0f, selVal = 0.0f;
        int selIdx = 0;
        #pragma unroll
        for (int k = 0; k < TOPK; k++) {
            float v = b0; int ix = lane;
            if (b1 > v) { v = b1; ix = lane + 32; }
            #pragma unroll
            for (int off = 16; off > 0; off >>= 1) {
                const float ov = __shfl_xor_sync(0xffffffffu, v, off);
                const int   oi = __shfl_xor_sync(0xffffffffu, ix, off);
                if (ov > v || (ov == v && oi < ix)) { v = ov; ix = oi; }
            }
            const float g0 = __shfl_sync(0xffffffffu, s0, ix & 31);
            const float g1 = __shfl_sync(0xffffffffu, s1, ix & 31);
            const float sv = (ix < 32) ? g0 : g1;
            denom += sv;
            if (lane == k) { selVal = sv; selIdx = ix; }
            if (lane == (ix & 31)) { if (ix < 32) b0 = -INFINITY; else b1 = -INFINITY; }
            if (lane == 0) atomicAdd(&shist[ix], 1);
        }
        const float scale = RSCALE / (denom + 1e-20f);
        const int tg = blockRow + tt;
        if (lane < TOPK) {
            out[tg * TOPK + lane]             = selVal * scale;
            out[NT * TOPK + tg * TOPK + lane] = (float)selIdx;
        }
    }
    __syncthreads();
    if (tid < NE) atomicAdd(&out[2 * NT * TOPK + tid], (float)shist[tid]);
}

extern "C" void kernel_launch(void* const* d_in, const int* in_sizes, int n_in,
                              void* d_out, int out_size) {
    const float* x    = (const float*)d_in[0];
    const float* w    = (const float*)d_in[1];
    const float* bias = (const float*)d_in[2];
    float* out = (float*)d_out;

    cudaFuncSetAttribute(router_kernel,
                         cudaFuncAttributeMaxDynamicSharedMemorySize, DSMEM);
    wprep_kernel<<<(NCHUNK * 3072 + 255) / 256, 256>>>(w, out);
    router_kernel<<<NCTA, NTHR, DSMEM>>>(x, bias, out);
}

// round 15
// speedup vs baseline: 1.2577x; 1.0312x over previous
#include <cuda_runtime.h>
#include <cuda_fp16.h>
#include <math.h>
#include <stdint.h>

#define NT 8192
#define DIMK 4096
#define NE 64
#define TOPK 8
#define RSCALE 2.5f
#define NCHUNK 64
#define NCTA 128
#define NTHR 512
#define TPC 64
#define SM_A 0            // A tiles: 2 bufs x 3 terms x 8192
#define SM_W 49152        // W frags: 2 bufs x 3 terms x 8192
#define DSMEM 98304
#define INV2048 4.8828125e-4f
#define INV2048SQ 2.384185791015625e-7f

__device__ uint2 w_img[NCHUNK * 3072];  // 1.5MB frag-layout 3-way W split

__device__ __forceinline__ uint32_t swz(uint32_t x) { return x ^ ((x >> 3) & 0x70u); }
__device__ __forceinline__ uint32_t smem_u32(const void* p) {
    uint32_t a;
    asm("{ .reg .u64 t; cvta.to.shared.u64 t, %1; cvt.u32.u64 %0, t; }" : "=r"(a) : "l"(p));
    return a;
}
// pack two fp32 -> one u32 holding half2 (lo = v0, hi = v1)
__device__ __forceinline__ uint32_t f2h2(float v0, float v1) {
    uint32_t r;
    asm("cvt.rn.f16x2.f32 %0, %2, %1;" : "=r"(r) : "f"(v0), "f"(v1));
    return r;
}
#define LDM(R, a) asm volatile( \
    "ldmatrix.sync.aligned.m8n8.x4.shared.b16 {%0,%1,%2,%3}, [%4];" \
    : "=r"((R)[0]), "=r"((R)[1]), "=r"((R)[2]), "=r"((R)[3]) : "r"(a))
#define MMA(C, A, B0, B1) asm volatile( \
    "mma.sync.aligned.m16n8k16.row.col.f32.f16.f16.f32 " \
    "{%0,%1,%2,%3},{%4,%5,%6,%7},{%8,%9},{%0,%1,%2,%3};" \
    : "+f"((C)[0]), "+f"((C)[1]), "+f"((C)[2]), "+f"((C)[3]) \
    : "r"((A)[0]), "r"((A)[1]), "r"((A)[2]), "r"((A)[3]), "r"(B0), "r"(B1))
#define LDS64(r0, r1, a) asm volatile("ld.shared.v2.u32 {%0,%1}, [%2];" \
    : "=r"(r0), "=r"(r1) : "r"(a))
#define CPA(d, s) asm volatile("cp.async.cg.shared.global [%0], [%1], 16;" :: "r"(d), "l"(s))
#define CPC() asm volatile("cp.async.commit_group;" ::: "memory")
#define CPW0() asm volatile("cp.async.wait_group 0;" ::: "memory")

// exact mask-truncation 3-way split of 2 floats -> 3 packed half2
// v = a + b/2048 + c/2048^2 exactly (13-bit r1, 11-bit b, <=2-bit c)
__device__ __forceinline__ void split3pk(float v0, float v1,
                                         uint32_t& ap, uint32_t& bp, uint32_t& cp) {
    float a0 = __uint_as_float(__float_as_uint(v0) & 0xFFFFE000u);
    float a1 = __uint_as_float(__float_as_uint(v1) & 0xFFFFE000u);
    float r0 = v0 - a0, r1 = v1 - a1;
    float b0 = __uint_as_float(__float_as_uint(r0) & 0xFFFFE000u);
    float b1 = __uint_as_float(__float_as_uint(r1) & 0xFFFFE000u);
    float c0 = r0 - b0, c1 = r1 - b1;
    ap = f2h2(a0, a1);
    bp = f2h2(b0 * 2048.0f, b1 * 2048.0f);
    cp = f2h2(c0 * 4194304.0f, c1 * 4194304.0f);
}

// W split into B-fragment-order image; also zeroes the histogram region
__global__ void wprep_kernel(const float* __restrict__ w, float* __restrict__ out) {
    int idx = blockIdx.x * blockDim.x + threadIdx.x;
    if (idx < NE) out[2 * NT * TOPK + idx] = 0.0f;
    if (idx >= NCHUNK * 3072) return;
    int c = idx / 3072, rem = idx % 3072;
    int t = rem >> 10;
    int rem2 = rem & 1023;
    int s = (rem2 >> 8) & 3, j = (rem2 >> 5) & 7, lane = rem2 & 31;
    int e = j * 8 + (lane >> 2);
    int k0 = c * 64 + s * 16 + (lane & 3) * 2;
    uint32_t pk[2];
    #pragma unroll
    for (int half8 = 0; half8 < 2; half8++) {
        int k = k0 + half8 * 8;
        uint32_t ap, bp, cp;
        split3pk(w[e * DIMK + k], w[e * DIMK + k + 1], ap, bp, cp);
        pk[half8] = (t == 0) ? ap : (t == 1 ? bp : cp);
    }
    uint2 o; o.x = pk[0]; o.y = pk[1];
    w_img[idx] = o;
}

__global__ void __launch_bounds__(NTHR, 1)
router_kernel(const float* __restrict__ x, const float* __restrict__ bias,
              float* __restrict__ out) {
    extern __shared__ char smem[];
    __shared__ int shist[NE];
    const uint32_t sb = smem_u32(smem);
    const int tid = threadIdx.x, wid = tid >> 5, lane = tid & 31;
    const int blockRow = blockIdx.x * TPC;
    const int pr = tid >> 3, pq = tid & 7;   // producer: row 0..63, 8-float col group
    const int mb = (wid & 3) * 16;           // m-tile (4)
    const int nh = (wid >> 2) & 1;           // n-half (2)
    const int ks = wid >> 3;                 // k-half (2)

    if (tid < NE) shist[tid] = 0;

    float Cs[4][4], Cf[4][4], C2[4][4], C3[4][4];
    #pragma unroll
    for (int j = 0; j < 4; j++)
        #pragma unroll
        for (int v = 0; v < 4; v++) { Cs[j][v] = 0; Cf[j][v] = 0; C2[j][v] = 0; C3[j][v] = 0; }

    // preload W chunk0
    {
        const char* src = (const char*)w_img + (size_t)tid * 48;
        uint32_t dst = sb + SM_W + tid * 48;
        #pragma unroll
        for (int q = 0; q < 3; q++) CPA(dst + q * 16, src + q * 16);
        CPC();
    }
    // load + convert chunk0
    uint32_t aw[4], bw[4], cw[4];
    {
        #pragma unroll
        for (int i = 0; i < 2; i++) {
            float4 v = *reinterpret_cast<const float4*>(
                &x[(size_t)(blockRow + pr) * DIMK + pq * 8 + i * 4]);
            split3pk(v.x, v.y, aw[i * 2], bw[i * 2], cw[i * 2]);
            split3pk(v.z, v.w, aw[i * 2 + 1], bw[i * 2 + 1], cw[i * 2 + 1]);
        }
    }

    const uint32_t lrow = (lane & 7) + ((lane >> 3) & 1) * 8;
    const uint32_t lcol16 = ((lane >> 4) & 1) * 16;
    const uint32_t soff = pr * 128 + pq * 16;

    for (int it = 0; it < NCHUNK; ++it) {
        const int b = it & 1;
        // STS pre-converted A tiles (critical path: 3 stores -> barrier)
        {
            char* A = smem + SM_A + b * 24576;
            *(uint4*)(A + swz(soff))         = make_uint4(aw[0], aw[1], aw[2], aw[3]);
            *(uint4*)(A + 8192 + swz(soff))  = make_uint4(bw[0], bw[1], bw[2], bw[3]);
            *(uint4*)(A + 16384 + swz(soff)) = make_uint4(cw[0], cw[1], cw[2], cw[3]);
        }
        CPW0();
        __syncthreads();
        if (it + 1 < NCHUNK) {
            const char* src = (const char*)w_img + (size_t)(it + 1) * 24576 + tid * 48;
            uint32_t dst = sb + SM_W + (b ^ 1) * 24576 + tid * 48;
            #pragma unroll
            for (int q = 0; q < 3; q++) CPA(dst + q * 16, src + q * 16);
            CPC();
        }
        // issue LDG for next x early (latency hidden under MMAs)
        float4 xn[2];
        if (it + 1 < NCHUNK) {
            const int kb = (it + 1) * 64;
            #pragma unroll
            for (int i = 0; i < 2; i++)
                xn[i] = *reinterpret_cast<const float4*>(
                    &x[(size_t)(blockRow + pr) * DIMK + kb + pq * 8 + i * 4]);
        }
        // consume: warp covers m16 x n32 x k32; jl-pair interleaved MMAs
        {
            const uint32_t Abase = sb + SM_A + b * 24576;
            const uint32_t Wbase = sb + SM_W + b * 24576;
            #pragma unroll
            for (int s2 = 0; s2 < 2; s2++) {
                const int sidx = ks * 2 + s2;
                uint32_t fa[4], fb[4], fc[4];
                uint32_t aoff = swz((mb + lrow) * 128 + sidx * 32 + lcol16);
                LDM(fa, Abase + aoff);
                LDM(fb, Abase + 8192 + aoff);
                LDM(fc, Abase + 16384 + aoff);
                #pragma unroll
                for (int jp = 0; jp < 2; jp++) {
                    const int p = jp * 2, q = jp * 2 + 1;
                    uint32_t wiP = ((sidx * 8 + nh * 4 + p) * 32 + lane) * 8;
                    uint32_t wiQ = ((sidx * 8 + nh * 4 + q) * 32 + lane) * 8;
                    uint32_t paw0, paw1, pbw0, pbw1, pcw0, pcw1;
                    uint32_t qaw0, qaw1, qbw0, qbw1, qcw0, qcw1;
                    LDS64(paw0, paw1, Wbase + wiP);
                    LDS64(qaw0, qaw1, Wbase + wiQ);
                    LDS64(pbw0, pbw1, Wbase + 8192 + wiP);
                    LDS64(qbw0, qbw1, Wbase + 8192 + wiQ);
                    LDS64(pcw0, pcw1, Wbase + 16384 + wiP);
                    LDS64(qcw0, qcw1, Wbase + 16384 + wiQ);
                    MMA(Cs[p], fa, paw0, paw1);
                    MMA(Cs[q], fa, qaw0, qaw1);
                    MMA(C2[p], fa, pbw0, pbw1);
                    MMA(C2[q], fa, qbw0, qbw1);
                    MMA(C3[p], fa, pcw0, pcw1);
                    MMA(C3[q], fa, qcw0, qcw1);
                    MMA(C2[p], fb, paw0, paw1);
                    MMA(C2[q], fb, qaw0, qaw1);
                    MMA(C3[p], fb, pbw0, pbw1);
                    MMA(C3[q], fb, qbw0, qbw1);
                    MMA(C3[p], fc, paw0, paw1);
                    MMA(C3[q], fc, qaw0, qaw1);
                }
            }
        }
        if ((it & 3) == 3) {
            #pragma unroll
            for (int j = 0; j < 4; j++)
                #pragma unroll
                for (int v = 0; v < 4; v++) { Cf[j][v] += Cs[j][v]; Cs[j][v] = 0; }
        }
        // convert next chunk (off critical path; overlaps tail of MMA latency)
        if (it + 1 < NCHUNK) {
            #pragma unroll
            for (int i = 0; i < 2; i++) {
                split3pk(xn[i].x, xn[i].y, aw[i * 2], bw[i * 2], cw[i * 2]);
                split3pk(xn[i].z, xn[i].w, aw[i * 2 + 1], bw[i * 2 + 1], cw[i * 2 + 1]);
            }
        }
    }

    // logits [64][65] in W region; two-phase combine of k-half partials
    float* logits = reinterpret_cast<float*>(smem + SM_W);
    if (ks == 0) {
        #pragma unroll
        for (int jl = 0; jl < 4; jl++) {
            const int r0 = mb + (lane >> 2);
            const int c0 = nh * 32 + jl * 8 + (lane & 3) * 2;
            #pragma unroll
            for (int v = 0; v < 4; v++) {
                const int rr = r0 + (v >> 1) * 8, cc = c0 + (v & 1);
                logits[rr * 65 + cc] =
                    Cf[jl][v] + C2[jl][v] * INV2048 + C3[jl][v] * INV2048SQ;
            }
        }
    }
    __syncthreads();
    if (ks == 1) {
        #pragma unroll
        for (int jl = 0; jl < 4; jl++) {
            const int r0 = mb + (lane >> 2);
            const int c0 = nh * 32 + jl * 8 + (lane & 3) * 2;
            #pragma unroll
            for (int v = 0; v < 4; v++) {
                const int rr = r0 + (v >> 1) * 8, cc = c0 + (v & 1);
                logits[rr * 65 + cc] +=
                    Cf[jl][v] + C2[jl][v] * INV2048 + C3[jl][v] * INV2048SQ;
            }
        }
    }
    __syncthreads();

    // routing: 16 warps x 4 tokens
    const float bias0 = bias[lane];
    const float bias1 = bias[lane + 32];
    for (int tt = wid * 4; tt < wid * 4 + 4; tt++) {
        const float l0 = logits[tt * 65 + lane];
        const float l1 = logits[tt * 65 + lane + 32];
        const float s0 = 1.0f / (1.0f + expf(-l0));
        const float s1 = 1.0f / (1.0f + expf(-l1));
        float b0 = s0 + bias0, b1 = s1 + bias1;
        float denom = 0.0f, selVal = 0.0f;
        int selIdx = 0;
        #pragma unroll
        for (int k = 0; k < TOPK; k++) {
            float v = b0; int ix = lane;
            if (b1 > v) { v = b1; ix = lane + 32; }
            #pragma unroll
            for (int off = 16; off > 0; off >>= 1) {
                const float ov = __shfl_xor_sync(0xffffffffu, v, off);
                const int   oi = __shfl_xor_sync(0xffffffffu, ix, off);
                if (ov > v || (ov == v && oi < ix)) { v = ov; ix = oi; }
            }
            const float g0 = __shfl_sync(0xffffffffu, s0, ix & 31);
            const float g1 = __shfl_sync(0xffffffffu, s1, ix & 31);
            const float sv = (ix < 32) ? g0 : g1;
            denom += sv;
            if (lane == k) { selVal = sv; selIdx = ix; }
            if (lane == (ix & 31)) { if (ix < 32) b0 = -INFINITY; else b1 = -INFINITY; }
            if (lane == 0) atomicAdd(&shist[ix], 1);
        }
        const float scale = RSCALE / (denom + 1e-20f);
        const int tg = blockRow + tt;
        if (lane < TOPK) {
            out[tg * TOPK + lane]             = selVal * scale;
            out[NT * TOPK + tg * TOPK + lane] = (float)selIdx;
        }
    }
    __syncthreads();
    if (tid < NE) atomicAdd(&out[2 * NT * TOPK + tid], (float)shist[tid]);
}

extern "C" void kernel_launch(void* const* d_in, const int* in_sizes, int n_in,
                              void* d_out, int out_size) {
    const float* x    = (const float*)d_in[0];
    const float* w    = (const float*)d_in[1];
    const float* bias = (const float*)d_in[2];
    float* out = (float*)d_out;

    cudaFuncSetAttribute(router_kernel,
                         cudaFuncAttributeMaxDynamicSharedMemorySize, DSMEM);
    wprep_kernel<<<(NCHUNK * 3072 + 255) / 256, 256>>>(w, out);
    router_kernel<<<NCTA, NTHR, DSMEM>>>(x, bias, out);
}